// round 1
// baseline (speedup 1.0000x reference)
#include <cuda_runtime.h>

#define NHEAD 4
#define NEG_SLOPE 0.2f

// ---------------- scratch (allocation-free: __device__ globals) ----------------
// B=1024, fanouts 10/25, F_in=256, F1=512, D=128
__device__ float g_y1 [10240 * NHEAD * 256];  // level-1 aggregated features   (42 MB)
__device__ float g_h1 [10240 * 512];          // level-1 GAT output            (21 MB)
__device__ float g_y0 [1024  * NHEAD * 256];  // level-0 layer-0 aggregated    (4 MB)
__device__ float g_h0a[1024  * 512];          // level-0 layer-0 output        (2 MB)
__device__ float g_y2 [1024  * NHEAD * 512];  // level-0 layer-1 aggregated    (8 MB)
__device__ float g_h0b[1024  * 512];          // level-0 layer-1 output        (2 MB)

// ---------------- fused attention + aggregation ----------------
// One CTA per (item). Computes per-head attention over [self; S neighbors] and
// the attention-weighted feature aggregate y[item][h][f]  (h-major, F per head).
template <int F>
__global__ void gat_attn_agg(const float* __restrict__ x_self,
                             const float* __restrict__ x_neigh,
                             const float* __restrict__ a_self,
                             const float* __restrict__ a_neigh,
                             float* __restrict__ y,
                             int S)
{
    extern __shared__ float sm[];
    const int item = blockIdx.x;
    const int tid  = threadIdx.x;
    const int NT   = 256;

    float* sx     = sm;                       // (S+1)*F   : x_all rows
    float* sanb   = sx   + (S + 1) * F;       // NHEAD*F   : a_neigh
    float* sasf   = sanb + NHEAD * F;         // NHEAD*F   : a_self
    float* slog   = sasf + NHEAD * F;         // (S+1)*NHEAD : logits -> attn
    float* slself = slog + (S + 1) * NHEAD;   // NHEAD

    // stage attention vectors
    for (int i = tid; i < NHEAD * F; i += NT) { sanb[i] = a_neigh[i]; sasf[i] = a_self[i]; }
    // stage x_all = [self; neighbors]
    {
        const float4* xs4 = (const float4*)(x_self + (long)item * F);
        for (int i = tid; i < F / 4; i += NT) ((float4*)sx)[i] = xs4[i];
        const float4* xn4 = (const float4*)(x_neigh + (long)item * S * F);
        float4* dst = (float4*)(sx + F);
        for (int i = tid; i < S * F / 4; i += NT) dst[i] = xn4[i];
    }
    __syncthreads();

    // logits: task t in [0, S+2): t<S+1 -> x_all[t] . a_neigh ; t==S+1 -> self . a_self
    const int w = tid >> 5, l = tid & 31;
    for (int t = w; t < S + 2; t += 8) {
        const float* row = (t < S + 1) ? (sx + t * F) : sx;
        const float* av  = (t < S + 1) ? sanb : sasf;
        float a0 = 0.f, a1 = 0.f, a2 = 0.f, a3 = 0.f;
        for (int f = l; f < F; f += 32) {
            float xv = row[f];
            a0 += xv * av[0 * F + f];
            a1 += xv * av[1 * F + f];
            a2 += xv * av[2 * F + f];
            a3 += xv * av[3 * F + f];
        }
        #pragma unroll
        for (int o = 16; o > 0; o >>= 1) {
            a0 += __shfl_down_sync(0xffffffffu, a0, o);
            a1 += __shfl_down_sync(0xffffffffu, a1, o);
            a2 += __shfl_down_sync(0xffffffffu, a2, o);
            a3 += __shfl_down_sync(0xffffffffu, a3, o);
        }
        if (l == 0) {
            if (t < S + 1) {
                slog[t * NHEAD + 0] = a0; slog[t * NHEAD + 1] = a1;
                slog[t * NHEAD + 2] = a2; slog[t * NHEAD + 3] = a3;
            } else {
                slself[0] = a0; slself[1] = a1; slself[2] = a2; slself[3] = a3;
            }
        }
    }
    __syncthreads();

    // leaky-relu + softmax over S+1 (tiny; one thread per head)
    if (tid < NHEAD) {
        const int h = tid;
        const float ls = slself[h];
        float m = -1e30f;
        for (int s = 0; s <= S; s++) {
            float z = ls + slog[s * NHEAD + h];
            z = (z >= 0.f) ? z : NEG_SLOPE * z;
            slog[s * NHEAD + h] = z;
            m = fmaxf(m, z);
        }
        float sum = 0.f;
        for (int s = 0; s <= S; s++) {
            float e = __expf(slog[s * NHEAD + h] - m);
            slog[s * NHEAD + h] = e;
            sum += e;
        }
        const float inv = 1.f / sum;
        for (int s = 0; s <= S; s++) slog[s * NHEAD + h] *= inv;
    }
    __syncthreads();

    // aggregation: y[item][h][f] = sum_s attn[s][h] * x_all[s][f]
    float* yo = y + (long)item * NHEAD * F;
    for (int f = tid; f < F; f += NT) {
        float a0 = 0.f, a1 = 0.f, a2 = 0.f, a3 = 0.f;
        for (int s = 0; s <= S; s++) {
            const float xv = sx[s * F + f];
            const float* at = slog + s * NHEAD;
            a0 += at[0] * xv; a1 += at[1] * xv; a2 += at[2] * xv; a3 += at[3] * xv;
        }
        yo[0 * F + f] = a0; yo[1 * F + f] = a1; yo[2 * F + f] = a2; yo[3 * F + f] = a3;
    }
}

// ---------------- generic tiled fp32 GEMM ----------------
// C[m][ccol + n] = sum_k A[m][k] * B[k][n], per "head" z (offsets via strides).
// BM=BN=128, BK=16, 256 threads, 8x8 microtile per thread.
#define BM 128
#define BN 128
#define BK 16

__global__ __launch_bounds__(256)
void gemm128(const float* __restrict__ A, const float* __restrict__ B,
             float* __restrict__ C,
             int K, int lda, int ldb, int ldc,
             int aStrideH, int bStrideH, int cColPerH)
{
    const int h = blockIdx.z;
    A += (long)h * aStrideH;
    B += (long)h * bStrideH;
    const int bm  = blockIdx.x * BM;
    const int bnB = blockIdx.y * BN;

    __shared__ float As[BK][BM];
    __shared__ float Bs[BK][BN];

    const int tid = threadIdx.x;
    const int tx = tid & 15, ty = tid >> 4;

    float acc[8][8];
    #pragma unroll
    for (int i = 0; i < 8; i++)
        #pragma unroll
        for (int j = 0; j < 8; j++) acc[i][j] = 0.f;

    for (int kb = 0; kb < K; kb += BK) {
        #pragma unroll
        for (int i = 0; i < 2; i++) {               // A: 128 rows x 16 k (transposed store)
            const int idx = tid + i * 256;
            const int row = idx >> 2;
            const int k4  = (idx & 3) << 2;
            float4 v = *(const float4*)(A + (long)(bm + row) * lda + kb + k4);
            As[k4 + 0][row] = v.x; As[k4 + 1][row] = v.y;
            As[k4 + 2][row] = v.z; As[k4 + 3][row] = v.w;
        }
        #pragma unroll
        for (int i = 0; i < 2; i++) {               // B: 16 k x 128 n
            const int idx = tid + i * 256;
            const int kk = idx >> 5;
            const int nn = (idx & 31) << 2;
            *(float4*)&Bs[kk][nn] = *(const float4*)(B + (long)(kb + kk) * ldb + bnB + nn);
        }
        __syncthreads();

        #pragma unroll
        for (int k = 0; k < BK; k++) {
            float a[8], b[8];
            *(float4*)&a[0] = *(float4*)&As[k][ty * 8];
            *(float4*)&a[4] = *(float4*)&As[k][ty * 8 + 4];
            *(float4*)&b[0] = *(float4*)&Bs[k][tx * 8];
            *(float4*)&b[4] = *(float4*)&Bs[k][tx * 8 + 4];
            #pragma unroll
            for (int i = 0; i < 8; i++)
                #pragma unroll
                for (int j = 0; j < 8; j++)
                    acc[i][j] += a[i] * b[j];
        }
        __syncthreads();
    }

    const int ccol = bnB + h * cColPerH;
    #pragma unroll
    for (int i = 0; i < 8; i++) {
        float* cr = C + (long)(bm + ty * 8 + i) * ldc + ccol + tx * 8;
        *(float4*)cr       = make_float4(acc[i][0], acc[i][1], acc[i][2], acc[i][3]);
        *(float4*)(cr + 4) = make_float4(acc[i][4], acc[i][5], acc[i][6], acc[i][7]);
    }
}

// ---------------- launch ----------------
static float* sym_addr(const void* symbol)
{
    void* p = nullptr;
    cudaGetSymbolAddress(&p, symbol);
    return (float*)p;
}

extern "C" void kernel_launch(void* const* d_in, const int* in_sizes, int n_in,
                              void* d_out, int out_size)
{
    const float* x0  = (const float*)d_in[0];  // (B, 1, 256)
    const float* x1  = (const float*)d_in[1];  // (B, 10, 256)
    const float* x2  = (const float*)d_in[2];  // (B, 250, 256)
    const float* w0  = (const float*)d_in[3];  // (4, 256, 128)
    const float* a0s = (const float*)d_in[4];  // (4, 256)
    const float* a0n = (const float*)d_in[5];  // (4, 256)
    const float* w1  = (const float*)d_in[6];  // (4, 512, 128)
    const float* a1s = (const float*)d_in[7];  // (4, 512)
    const float* a1n = (const float*)d_in[8];  // (4, 512)
    const float* fcw = (const float*)d_in[9];  // (512, 256)
    float* out = (float*)d_out;                // (B, 256)

    const int Bn = in_sizes[0] / 256;          // 1024

    float* y1  = sym_addr(g_y1);
    float* h1  = sym_addr(g_h1);
    float* y0  = sym_addr(g_y0);
    float* h0a = sym_addr(g_h0a);
    float* y2  = sym_addr(g_y2);
    float* h0b = sym_addr(g_h0b);

    const int S1 = 25, S0 = 10;

    // ---- level 1: h1 = GAT(x1, x2; w0) ----
    {
        size_t smem = (size_t)((S1 + 1) * 256 + 2 * NHEAD * 256 + (S1 + 1) * NHEAD + NHEAD) * 4;
        gat_attn_agg<256><<<Bn * 10, 256, smem>>>(x1, x2, a0s, a0n, y1, S1);
        // h1[m][h*128+d] = y1[m][h][:] @ w0[h]   (M=10240, K=256, N=128 per head)
        gemm128<<<dim3(Bn * 10 / 128, 1, NHEAD), 256>>>(
            y1, w0, h1, 256, NHEAD * 256, 128, 512, 256, 256 * 128, 128);
    }

    // ---- level 0, layer 0: h0a = GAT(x0, x1; w0) ----
    {
        size_t smem = (size_t)((S0 + 1) * 256 + 2 * NHEAD * 256 + (S0 + 1) * NHEAD + NHEAD) * 4;
        gat_attn_agg<256><<<Bn, 256, smem>>>(x0, x1, a0s, a0n, y0, S0);
        gemm128<<<dim3(Bn / 128, 1, NHEAD), 256>>>(
            y0, w0, h0a, 256, NHEAD * 256, 128, 512, 256, 256 * 128, 128);
    }

    // ---- level 0, layer 1: h0b = GAT(h0a, h1; w1) ----
    {
        size_t smem = (size_t)((S0 + 1) * 512 + 2 * NHEAD * 512 + (S0 + 1) * NHEAD + NHEAD) * 4;
        gat_attn_agg<512><<<Bn, 256, smem>>>(h0a, h1, a1s, a1n, y2, S0);
        gemm128<<<dim3(Bn / 128, 1, NHEAD), 256>>>(
            y2, w1, h0b, 512, NHEAD * 512, 128, 512, 512, 512 * 128, 128);
    }

    // ---- final projection: out = h0b @ fc_w  (M=1024, K=512, N=256) ----
    gemm128<<<dim3(Bn / 128, 2, 1), 256>>>(
        h0b, fcw, out, 512, 512, 256, 256, 0, 0, 0);
}

// round 2
// speedup vs baseline: 1.3543x; 1.3543x over previous
#include <cuda_runtime.h>

#define NHEAD 4
#define NEG_SLOPE 0.2f

// ---------------- scratch (allocation-free: __device__ globals) ----------------
// B=1024, fanouts 10/25, F_in=256, F1=512, D=128
__device__ float g_y1 [10240 * NHEAD * 256];  // level-1 aggregated features
__device__ float g_h1 [10240 * 512];          // level-1 GAT output
__device__ float g_y0 [1024  * NHEAD * 256];  // level-0 layer-0 aggregated
__device__ float g_h0a[1024  * 512];          // level-0 layer-0 output
__device__ float g_y2 [1024  * NHEAD * 512];  // level-0 layer-1 aggregated
__device__ float g_h0b[1024  * 512];          // level-0 layer-1 output

// ---------------- f32x2 packed-math helpers (sm_100+) ----------------
__device__ __forceinline__ unsigned long long pack2(float lo, float hi) {
    unsigned long long r;
    asm("mov.b64 %0, {%1,%2};" : "=l"(r) : "f"(lo), "f"(hi));
    return r;
}
__device__ __forceinline__ void unpack2(unsigned long long v, float& lo, float& hi) {
    asm("mov.b64 {%0,%1}, %2;" : "=f"(lo), "=f"(hi) : "l"(v));
}
__device__ __forceinline__ void fma2(unsigned long long& c, unsigned long long a,
                                     unsigned long long b) {
    asm("fma.rn.f32x2 %0, %1, %2, %0;" : "+l"(c) : "l"(a), "l"(b));
}

// ---------------- fused attention + aggregation ----------------
// One CTA per item. Per-head attention over [self; S neighbors], writes the
// attention-weighted aggregate y[item][h][f] (h-major).
template <int F>
__global__ void gat_attn_agg(const float* __restrict__ x_self,
                             const float* __restrict__ x_neigh,
                             const float* __restrict__ a_self,
                             const float* __restrict__ a_neigh,
                             float* __restrict__ y,
                             int S)
{
    extern __shared__ float sm[];
    const int item = blockIdx.x;
    const int tid  = threadIdx.x;
    const int NT   = 256;

    float* sx     = sm;                       // (S+1)*F   : x_all rows
    float* sanb   = sx   + (S + 1) * F;       // NHEAD*F   : a_neigh
    float* sasf   = sanb + NHEAD * F;         // NHEAD*F   : a_self
    float* slog   = sasf + NHEAD * F;         // (S+1)*NHEAD : logits -> attn
    float* slself = slog + (S + 1) * NHEAD;   // NHEAD

    for (int i = tid; i < NHEAD * F; i += NT) { sanb[i] = a_neigh[i]; sasf[i] = a_self[i]; }
    {
        const float4* xs4 = (const float4*)(x_self + (long)item * F);
        for (int i = tid; i < F / 4; i += NT) ((float4*)sx)[i] = xs4[i];
        const float4* xn4 = (const float4*)(x_neigh + (long)item * S * F);
        float4* dst = (float4*)(sx + F);
        for (int i = tid; i < S * F / 4; i += NT) dst[i] = xn4[i];
    }
    __syncthreads();

    const int w = tid >> 5, l = tid & 31;
    for (int t = w; t < S + 2; t += 8) {
        const float* row = (t < S + 1) ? (sx + t * F) : sx;
        const float* av  = (t < S + 1) ? sanb : sasf;
        float a0 = 0.f, a1 = 0.f, a2 = 0.f, a3 = 0.f;
        for (int f = l; f < F; f += 32) {
            float xv = row[f];
            a0 += xv * av[0 * F + f];
            a1 += xv * av[1 * F + f];
            a2 += xv * av[2 * F + f];
            a3 += xv * av[3 * F + f];
        }
        #pragma unroll
        for (int o = 16; o > 0; o >>= 1) {
            a0 += __shfl_down_sync(0xffffffffu, a0, o);
            a1 += __shfl_down_sync(0xffffffffu, a1, o);
            a2 += __shfl_down_sync(0xffffffffu, a2, o);
            a3 += __shfl_down_sync(0xffffffffu, a3, o);
        }
        if (l == 0) {
            if (t < S + 1) {
                slog[t * NHEAD + 0] = a0; slog[t * NHEAD + 1] = a1;
                slog[t * NHEAD + 2] = a2; slog[t * NHEAD + 3] = a3;
            } else {
                slself[0] = a0; slself[1] = a1; slself[2] = a2; slself[3] = a3;
            }
        }
    }
    __syncthreads();

    if (tid < NHEAD) {
        const int h = tid;
        const float ls = slself[h];
        float m = -1e30f;
        for (int s = 0; s <= S; s++) {
            float z = ls + slog[s * NHEAD + h];
            z = (z >= 0.f) ? z : NEG_SLOPE * z;
            slog[s * NHEAD + h] = z;
            m = fmaxf(m, z);
        }
        float sum = 0.f;
        for (int s = 0; s <= S; s++) {
            float e = __expf(slog[s * NHEAD + h] - m);
            slog[s * NHEAD + h] = e;
            sum += e;
        }
        const float inv = 1.f / sum;
        for (int s = 0; s <= S; s++) slog[s * NHEAD + h] *= inv;
    }
    __syncthreads();

    float* yo = y + (long)item * NHEAD * F;
    for (int f = tid; f < F; f += NT) {
        float a0 = 0.f, a1 = 0.f, a2 = 0.f, a3 = 0.f;
        for (int s = 0; s <= S; s++) {
            const float xv = sx[s * F + f];
            const float* at = slog + s * NHEAD;
            a0 += at[0] * xv; a1 += at[1] * xv; a2 += at[2] * xv; a3 += at[3] * xv;
        }
        yo[0 * F + f] = a0; yo[1 * F + f] = a1; yo[2 * F + f] = a2; yo[3 * F + f] = a3;
    }
}

// ---------------- f32x2 tiled GEMM (double-buffered) ----------------
// C[m][h*cColPerH + n] = sum_k A[h*aStrideH + m*lda + k] * B[h*bStrideH + k*ldb + n]
// 256 threads; microtile TM x TN per thread; accumulators are f32x2 pairs along M.
template<int BM, int BN, int TM, int TN>
__global__ __launch_bounds__(256)
void gemm_f32x2(const float* __restrict__ A, const float* __restrict__ B,
                float* __restrict__ C,
                int K, int lda, int ldb, int ldc,
                int aStrideH, int bStrideH, int cColPerH)
{
    constexpr int BK  = 16;
    constexpr int NT  = 256;
    constexpr int TX  = BN / TN;          // threads along n
    constexpr int MP  = TM / 2;           // m-pairs per thread
    constexpr int nA4 = BM * BK / 4 / NT; // float4 A loads per thread per stage
    constexpr int nB4 = BK * BN / 4 / NT;

    const int h = blockIdx.z;
    A += (long)h * aStrideH;
    B += (long)h * bStrideH;
    const int bm = blockIdx.x * BM;
    const int bn = blockIdx.y * BN;

    __shared__ float As[2][BK][BM];   // transposed A tile: As[k][m]
    __shared__ float Bs[2][BK][BN];

    const int tid = threadIdx.x;
    const int tx  = tid % TX;
    const int ty  = tid / TX;

    unsigned long long acc[MP][TN];
    #pragma unroll
    for (int i = 0; i < MP; i++)
        #pragma unroll
        for (int j = 0; j < TN; j++) acc[i][j] = 0ull;

    // load-index precompute
    int arow[nA4], akq[nA4], bkk[nB4], bnn[nB4];
    #pragma unroll
    for (int i = 0; i < nA4; i++) {
        const int id = tid + i * NT;
        arow[i] = id / (BK / 4);
        akq[i]  = (id % (BK / 4)) * 4;
    }
    #pragma unroll
    for (int i = 0; i < nB4; i++) {
        const int id = tid + i * NT;
        bkk[i] = id / (BN / 4);
        bnn[i] = (id % (BN / 4)) * 4;
    }

    float4 ra[nA4], rb[nB4];
    const int nk = K / BK;

    auto ldg = [&](int kb) {
        #pragma unroll
        for (int i = 0; i < nA4; i++)
            ra[i] = *(const float4*)(A + (long)(bm + arow[i]) * lda + kb * BK + akq[i]);
        #pragma unroll
        for (int i = 0; i < nB4; i++)
            rb[i] = *(const float4*)(B + (long)(kb * BK + bkk[i]) * ldb + bn + bnn[i]);
    };
    auto sts = [&](int s) {
        #pragma unroll
        for (int i = 0; i < nA4; i++) {
            As[s][akq[i] + 0][arow[i]] = ra[i].x;
            As[s][akq[i] + 1][arow[i]] = ra[i].y;
            As[s][akq[i] + 2][arow[i]] = ra[i].z;
            As[s][akq[i] + 3][arow[i]] = ra[i].w;
        }
        #pragma unroll
        for (int i = 0; i < nB4; i++)
            *(float4*)&Bs[s][bkk[i]][bnn[i]] = rb[i];
    };
    auto compute = [&](int s) {
        #pragma unroll
        for (int k = 0; k < BK; k++) {
            float a[TM], b[TN];
            #pragma unroll
            for (int q = 0; q < TM / 4; q++)
                *(float4*)&a[q * 4] = *(const float4*)&As[s][k][ty * TM + q * 4];
            #pragma unroll
            for (int q = 0; q < TN / 4; q++)
                *(float4*)&b[q * 4] = *(const float4*)&Bs[s][k][tx * TN + q * 4];
            unsigned long long ap[MP], bp[TN];
            #pragma unroll
            for (int i = 0; i < MP; i++) ap[i] = pack2(a[2 * i], a[2 * i + 1]);
            #pragma unroll
            for (int j = 0; j < TN; j++) bp[j] = pack2(b[j], b[j]);
            #pragma unroll
            for (int i = 0; i < MP; i++)
                #pragma unroll
                for (int j = 0; j < TN; j++)
                    fma2(acc[i][j], ap[i], bp[j]);
        }
    };

    ldg(0);
    sts(0);
    __syncthreads();

    for (int kb = 0; kb < nk; kb++) {
        const int cur = kb & 1;
        if (kb + 1 < nk) ldg(kb + 1);   // prefetch (latency hidden by compute)
        compute(cur);
        if (kb + 1 < nk) {
            sts(cur ^ 1);
            __syncthreads();
        }
    }

    const int ccol = bn + h * cColPerH;
    #pragma unroll
    for (int ip = 0; ip < MP; ip++) {
        float lo[TN], hi[TN];
        #pragma unroll
        for (int j = 0; j < TN; j++) unpack2(acc[ip][j], lo[j], hi[j]);
        float* cr0 = C + (long)(bm + ty * TM + 2 * ip)     * ldc + ccol + tx * TN;
        float* cr1 = C + (long)(bm + ty * TM + 2 * ip + 1) * ldc + ccol + tx * TN;
        #pragma unroll
        for (int q = 0; q < TN / 4; q++) {
            *(float4*)(cr0 + q * 4) = make_float4(lo[q*4+0], lo[q*4+1], lo[q*4+2], lo[q*4+3]);
            *(float4*)(cr1 + q * 4) = make_float4(hi[q*4+0], hi[q*4+1], hi[q*4+2], hi[q*4+3]);
        }
    }
}

// ---------------- launch ----------------
static float* sym_addr(const void* symbol)
{
    void* p = nullptr;
    cudaGetSymbolAddress(&p, symbol);
    return (float*)p;
}

extern "C" void kernel_launch(void* const* d_in, const int* in_sizes, int n_in,
                              void* d_out, int out_size)
{
    const float* x0  = (const float*)d_in[0];  // (B, 1, 256)
    const float* x1  = (const float*)d_in[1];  // (B, 10, 256)
    const float* x2  = (const float*)d_in[2];  // (B, 250, 256)
    const float* w0  = (const float*)d_in[3];  // (4, 256, 128)
    const float* a0s = (const float*)d_in[4];  // (4, 256)
    const float* a0n = (const float*)d_in[5];  // (4, 256)
    const float* w1  = (const float*)d_in[6];  // (4, 512, 128)
    const float* a1s = (const float*)d_in[7];  // (4, 512)
    const float* a1n = (const float*)d_in[8];  // (4, 512)
    const float* fcw = (const float*)d_in[9];  // (512, 256)
    float* out = (float*)d_out;                // (B, 256)

    const int Bn = in_sizes[0] / 256;          // 1024

    float* y1  = sym_addr(g_y1);
    float* h1  = sym_addr(g_h1);
    float* y0  = sym_addr(g_y0);
    float* h0a = sym_addr(g_h0a);
    float* y2  = sym_addr(g_y2);
    float* h0b = sym_addr(g_h0b);

    const int S1 = 25, S0 = 10;

    // ---- level 1: h1 = GAT(x1, x2; w0) ----
    {
        size_t smem = (size_t)((S1 + 1) * 256 + 2 * NHEAD * 256 + (S1 + 1) * NHEAD + NHEAD) * 4;
        gat_attn_agg<256><<<Bn * 10, 256, smem>>>(x1, x2, a0s, a0n, y1, S1);
        // h1[m][h*128+d] = y1[m][h][:] @ w0[h]   (M=10240, K=256, N=128/head)
        gemm_f32x2<128, 128, 8, 8><<<dim3(Bn * 10 / 128, 1, NHEAD), 256>>>(
            y1, w0, h1, 256, NHEAD * 256, 128, 512, 256, 256 * 128, 128);
    }

    // ---- level 0, layer 0: h0a = GAT(x0, x1; w0) ----
    {
        size_t smem = (size_t)((S0 + 1) * 256 + 2 * NHEAD * 256 + (S0 + 1) * NHEAD + NHEAD) * 4;
        gat_attn_agg<256><<<Bn, 256, smem>>>(x0, x1, a0s, a0n, y0, S0);
        gemm_f32x2<64, 64, 4, 4><<<dim3(Bn / 64, 128 / 64, NHEAD), 256>>>(
            y0, w0, h0a, 256, NHEAD * 256, 128, 512, 256, 256 * 128, 128);
    }

    // ---- level 0, layer 1: h0b = GAT(h0a, h1; w1) ----
    {
        size_t smem = (size_t)((S0 + 1) * 512 + 2 * NHEAD * 512 + (S0 + 1) * NHEAD + NHEAD) * 4;
        gat_attn_agg<512><<<Bn, 256, smem>>>(h0a, h1, a1s, a1n, y2, S0);
        gemm_f32x2<64, 64, 4, 4><<<dim3(Bn / 64, 128 / 64, NHEAD), 256>>>(
            y2, w1, h0b, 512, NHEAD * 512, 128, 512, 512, 512 * 128, 128);
    }

    // ---- final projection: out = h0b @ fc_w  (M=1024, K=512, N=256) ----
    gemm_f32x2<64, 64, 4, 4><<<dim3(Bn / 64, 256 / 64, 1), 256>>>(
        h0b, fcw, out, 512, 512, 256, 256, 0, 0, 0);
}